// round 2
// baseline (speedup 1.0000x reference)
#include <cuda_runtime.h>
#include <cuda_bf16.h>
#include <cstdint>

// ============================================================================
// BitLinear: x[4,8192,1024] f32, W[1024,1024] f32, gamma/beta[1024]
// out = (scale_act*alpha) * (Qint @ T^T);  M=32768, K=1024, N=1024
// Qint = round(clip(LN(x)/scale, -127, 127))  -> int8 exact
// T = ternary{-1,0,1}                         -> int8 exact
// GEMM in s32 via mma.sync (IMMA), scale in f32 epilogue.
// ============================================================================

#define M_ROWS 32768
#define K_DIM  1024
#define N_DIM  1024

// ---------------- device scratch ----------------
__device__ float         g_mu[M_ROWS];
__device__ float         g_rstd[M_ROWS];
__device__ unsigned int  g_absmax_bits;
__device__ float         g_wsum_abs;
__device__ float         g_wsum_absmask;
__device__ float         g_wsum_maskcnt;
__device__ float         g_outscale;
__device__ float         g_qinv;
__device__ int8_t        g_q[(size_t)M_ROWS * K_DIM];   // 32 MB
__device__ int8_t        g_t[(size_t)N_DIM * K_DIM];    // 1 MB

// ---------------- PTX helpers (baseline ISA only: sm_80-class) --------------
__device__ __forceinline__ uint32_t smem_u32(const void* p) {
    uint32_t a;
    asm("{ .reg .u64 t; cvta.to.shared.u64 t, %1; cvt.u32.u64 %0, t; }"
        : "=r"(a) : "l"(p));
    return a;
}
__device__ __forceinline__ void ldm_x4(uint32_t* r, uint32_t addr) {
    asm volatile("ldmatrix.sync.aligned.m8n8.x4.shared.b16 {%0,%1,%2,%3}, [%4];"
                 : "=r"(r[0]), "=r"(r[1]), "=r"(r[2]), "=r"(r[3]) : "r"(addr));
}
__device__ __forceinline__ void mma_s8(int* c, const uint32_t* a, const uint32_t* b) {
    asm volatile(
        "mma.sync.aligned.m16n8k32.row.col.s32.s8.s8.s32 "
        "{%0,%1,%2,%3}, {%4,%5,%6,%7}, {%8,%9}, {%0,%1,%2,%3};"
        : "+r"(c[0]), "+r"(c[1]), "+r"(c[2]), "+r"(c[3])
        : "r"(a[0]), "r"(a[1]), "r"(a[2]), "r"(a[3]), "r"(b[0]), "r"(b[1]));
}
#define CP_ASYNC16(sm, gm)                                                   \
    asm volatile("cp.async.cg.shared.global [%0], [%1], 16;" ::              \
                 "r"(sm), "l"(__cvta_generic_to_global(gm)))
#define CP_COMMIT() asm volatile("cp.async.commit_group;" ::: "memory")
#define CP_WAIT(n)  asm volatile("cp.async.wait_group %0;" :: "n"(n) : "memory")

// ============================================================================
// Kernel 1: zero accumulators
// ============================================================================
__global__ void zero_kernel() {
    g_absmax_bits  = 0u;
    g_wsum_abs     = 0.0f;
    g_wsum_absmask = 0.0f;
    g_wsum_maskcnt = 0.0f;
}

// ============================================================================
// Kernel 2: LN stats per row + global absmax of normalized output
// ============================================================================
__global__ __launch_bounds__(256) void ln_stats_kernel(
    const float4* __restrict__ x4, const float4* __restrict__ gamma4,
    const float4* __restrict__ beta4) {
    const int row = blockIdx.x;
    const int tid = threadIdx.x;
    float4 v = x4[(size_t)row * 256 + tid];
    float s  = v.x + v.y + v.z + v.w;
    float ss = fmaf(v.x, v.x, fmaf(v.y, v.y, fmaf(v.z, v.z, v.w * v.w)));
#pragma unroll
    for (int o = 16; o > 0; o >>= 1) {
        s  += __shfl_xor_sync(0xffffffffu, s, o);
        ss += __shfl_xor_sync(0xffffffffu, ss, o);
    }
    __shared__ float rs[8], rss[8], bc[2], rm[8];
    const int w = tid >> 5, lane = tid & 31;
    if (lane == 0) { rs[w] = s; rss[w] = ss; }
    __syncthreads();
    if (tid == 0) {
        float ts = 0.f, tss = 0.f;
#pragma unroll
        for (int i = 0; i < 8; ++i) { ts += rs[i]; tss += rss[i]; }
        float mu  = ts * (1.0f / 1024.0f);
        float var = tss * (1.0f / 1024.0f) - mu * mu;
        float rstd = rsqrtf(var + 1e-5f);
        bc[0] = mu; bc[1] = rstd;
        g_mu[row] = mu; g_rstd[row] = rstd;
    }
    __syncthreads();
    const float mu = bc[0], rstd = bc[1];
    float4 g = gamma4[tid], b = beta4[tid];
    float m0 = fabsf(fmaf((v.x - mu) * rstd, g.x, b.x));
    float m1 = fabsf(fmaf((v.y - mu) * rstd, g.y, b.y));
    float m2 = fabsf(fmaf((v.z - mu) * rstd, g.z, b.z));
    float m3 = fabsf(fmaf((v.w - mu) * rstd, g.w, b.w));
    float mm = fmaxf(fmaxf(m0, m1), fmaxf(m2, m3));
#pragma unroll
    for (int o = 16; o > 0; o >>= 1)
        mm = fmaxf(mm, __shfl_xor_sync(0xffffffffu, mm, o));
    if (lane == 0) rm[w] = mm;
    __syncthreads();
    if (tid == 0) {
        float t = rm[0];
#pragma unroll
        for (int i = 1; i < 8; ++i) t = fmaxf(t, rm[i]);
        atomicMax(&g_absmax_bits, __float_as_uint(t));  // t >= 0: bit order OK
    }
}

// ============================================================================
// Kernel 3: sum |W|
// ============================================================================
__global__ __launch_bounds__(256) void wabs_kernel(const float4* __restrict__ w4) {
    float s = 0.f;
    for (int i = blockIdx.x * blockDim.x + threadIdx.x; i < (N_DIM * K_DIM / 4);
         i += gridDim.x * blockDim.x) {
        float4 v = w4[i];
        s += fabsf(v.x) + fabsf(v.y) + fabsf(v.z) + fabsf(v.w);
    }
#pragma unroll
    for (int o = 16; o > 0; o >>= 1) s += __shfl_xor_sync(0xffffffffu, s, o);
    __shared__ float rr[8];
    if ((threadIdx.x & 31) == 0) rr[threadIdx.x >> 5] = s;
    __syncthreads();
    if (threadIdx.x == 0) {
        float t = 0.f;
#pragma unroll
        for (int i = 0; i < 8; ++i) t += rr[i];
        atomicAdd(&g_wsum_abs, t);
    }
}

// ============================================================================
// Kernel 4: ternarize W -> int8 {-1,0,+1}; reduce masked |W| sum + count
// ============================================================================
__global__ __launch_bounds__(256) void wtern_kernel(const float4* __restrict__ w4) {
    const int idx = blockIdx.x * 256 + threadIdx.x;
    const float delta = 0.7f * g_wsum_abs * (1.0f / (float)(N_DIM * K_DIM));
    float4 v = w4[idx];
    float a[4] = {v.x, v.y, v.z, v.w};
    int   t[4];
    float sa = 0.f, cnt = 0.f;
#pragma unroll
    for (int j = 0; j < 4; ++j) {
        float av = fabsf(a[j]);
        if (av > delta) {
            t[j] = (a[j] > 0.f) ? 1 : -1;
            sa += av; cnt += 1.0f;
        } else t[j] = 0;
    }
    uint32_t pk = (uint32_t)(t[0] & 0xff) | ((uint32_t)(t[1] & 0xff) << 8) |
                  ((uint32_t)(t[2] & 0xff) << 16) | ((uint32_t)t[3] << 24);
    reinterpret_cast<uint32_t*>(g_t)[idx] = pk;
#pragma unroll
    for (int o = 16; o > 0; o >>= 1) {
        sa  += __shfl_xor_sync(0xffffffffu, sa, o);
        cnt += __shfl_xor_sync(0xffffffffu, cnt, o);
    }
    __shared__ float ra[8], rc[8];
    if ((threadIdx.x & 31) == 0) { ra[threadIdx.x >> 5] = sa; rc[threadIdx.x >> 5] = cnt; }
    __syncthreads();
    if (threadIdx.x == 0) {
        float ta = 0.f, tc = 0.f;
#pragma unroll
        for (int i = 0; i < 8; ++i) { ta += ra[i]; tc += rc[i]; }
        atomicAdd(&g_wsum_absmask, ta);
        atomicAdd(&g_wsum_maskcnt, tc);
    }
}

// ============================================================================
// Kernel 5: finalize scalars
// ============================================================================
__global__ void finalize_kernel() {
    float amax  = fmaxf(__uint_as_float(g_absmax_bits), 1e-8f);
    float scale = amax * (1.0f / 127.0f);
    float alpha = g_wsum_absmask / fmaxf(g_wsum_maskcnt, 1.0f);
    g_outscale = scale * alpha;
    g_qinv     = 127.0f / amax;
}

// ============================================================================
// Kernel 6: quantize LN(x) -> int8 codes in [-127,127], packed 4/u32
// ============================================================================
__global__ __launch_bounds__(256) void quant_kernel(
    const float4* __restrict__ x4, const float4* __restrict__ gamma4,
    const float4* __restrict__ beta4) {
    const int idx = blockIdx.x * 256 + threadIdx.x;
    const int row = idx >> 8;
    const int c4  = idx & 255;
    const float mu = g_mu[row], rstd = g_rstd[row], inv = g_qinv;
    float4 v = x4[idx];
    float4 g = gamma4[c4], b = beta4[c4];
    int q0 = __float2int_rn(fminf(fmaxf(fmaf((v.x - mu) * rstd, g.x, b.x) * inv, -127.f), 127.f));
    int q1 = __float2int_rn(fminf(fmaxf(fmaf((v.y - mu) * rstd, g.y, b.y) * inv, -127.f), 127.f));
    int q2 = __float2int_rn(fminf(fmaxf(fmaf((v.z - mu) * rstd, g.z, b.z) * inv, -127.f), 127.f));
    int q3 = __float2int_rn(fminf(fmaxf(fmaf((v.w - mu) * rstd, g.w, b.w) * inv, -127.f), 127.f));
    uint32_t pk = (uint32_t)(q0 & 0xff) | ((uint32_t)(q1 & 0xff) << 8) |
                  ((uint32_t)(q2 & 0xff) << 16) | ((uint32_t)q3 << 24);
    reinterpret_cast<uint32_t*>(g_q)[idx] = pk;
}

// ============================================================================
// Kernel 7: int8 GEMM via mma.sync m16n8k32 (IMMA), s32 accum
// CTA tile 128x128, 8 warps (4M x 2N), warp tile 32x64
// K chunked by 128 B, 3-stage cp.async pipeline, xor-swizzled smem
// ============================================================================
#define GEMM_STAGES 3
#define STAGE_BYTES 32768                 // A 16KB + B 16KB
#define GEMM_SMEM   (GEMM_STAGES * STAGE_BYTES)   // 96 KB >= epilogue 69632 B
#define NK_CHUNKS   8                     // 1024 / 128

static __device__ __forceinline__ void load_stage(
    const uint8_t* __restrict__ Ag, const uint8_t* __restrict__ Bg,
    uint32_t sA, uint32_t sB, int kt, int tid) {
    const int koff = kt * 128;
#pragma unroll
    for (int i = 0; i < 4; ++i) {
        int v = i * 256 + tid;
        int row = v >> 3, c = v & 7;
        uint32_t sw = (uint32_t)(row * 128 + ((c ^ (row & 7)) << 4));
        size_t go = (size_t)row * K_DIM + koff + c * 16;
        CP_ASYNC16(sA + sw, Ag + go);
        CP_ASYNC16(sB + sw, Bg + go);
    }
}

__global__ __launch_bounds__(256, 2) void gemm_kernel(float* __restrict__ out) {
    extern __shared__ char smem[];
    const uint32_t smem_base = smem_u32(smem);
    const int tid = threadIdx.x;
    const int wid = tid >> 5, lane = tid & 31;
    const int warp_m = wid & 3, warp_n = wid >> 2;
    const int m0 = blockIdx.y * 128, n0 = blockIdx.x * 128;

    const uint8_t* Ag = reinterpret_cast<const uint8_t*>(g_q) + (size_t)m0 * K_DIM;
    const uint8_t* Bg = reinterpret_cast<const uint8_t*>(g_t) + (size_t)n0 * K_DIM;

    // prologue: prefetch chunks 0,1
    load_stage(Ag, Bg, smem_base, smem_base + 16384, 0, tid);
    CP_COMMIT();
    load_stage(Ag, Bg, smem_base + STAGE_BYTES, smem_base + STAGE_BYTES + 16384, 1, tid);
    CP_COMMIT();

    int C[2][8][4];
#pragma unroll
    for (int i = 0; i < 2; ++i)
#pragma unroll
        for (int j = 0; j < 8; ++j)
#pragma unroll
            for (int k = 0; k < 4; ++k) C[i][j][k] = 0;

    // per-lane ldmatrix addressing (precomputed)
    const int rA  = warp_m * 32 + (lane & 15);
    const int cA  = (lane >> 4);                   // 0/1 -> low/high 16B of kstep
    const int rBo = ((lane & 16) >> 1) + (lane & 7);
    const int cB  = (lane >> 3) & 1;

#pragma unroll 1
    for (int kt = 0; kt < NK_CHUNKS; ++kt) {
        CP_WAIT(1);
        __syncthreads();
        if (kt + 2 < NK_CHUNKS) {
            uint32_t sbase = smem_base + ((kt + 2) % GEMM_STAGES) * STAGE_BYTES;
            load_stage(Ag, Bg, sbase, sbase + 16384, kt + 2, tid);
        }
        CP_COMMIT();

        const uint32_t aB = smem_base + (kt % GEMM_STAGES) * STAGE_BYTES;
        const uint32_t bB = aB + 16384;
#pragma unroll
        for (int ks = 0; ks < 4; ++ks) {
            uint32_t a[2][4];
#pragma unroll
            for (int fm = 0; fm < 2; ++fm) {
                int row = rA + fm * 16;
                ldm_x4(a[fm], aB + row * 128 + (((ks * 2 + cA) ^ (row & 7)) << 4));
            }
            uint32_t b[4][4];
#pragma unroll
            for (int p = 0; p < 4; ++p) {
                int row = warp_n * 64 + p * 16 + rBo;
                ldm_x4(b[p], bB + row * 128 + (((ks * 2 + cB) ^ (row & 7)) << 4));
            }
#pragma unroll
            for (int fm = 0; fm < 2; ++fm)
#pragma unroll
                for (int p = 0; p < 4; ++p) {
                    mma_s8(C[fm][2 * p],     a[fm], &b[p][0]);
                    mma_s8(C[fm][2 * p + 1], a[fm], &b[p][2]);
                }
        }
        __syncthreads();
    }

    // ---------------- epilogue: s32 -> f32*scale, staged for coalesced STG ---
    const float osc = g_outscale;
    float* stg = reinterpret_cast<float*>(smem);   // 128 rows x stride 136 f32
    __syncthreads();
#pragma unroll
    for (int fm = 0; fm < 2; ++fm) {
        const int rbase = warp_m * 32 + fm * 16 + (lane >> 2);
#pragma unroll
        for (int fn = 0; fn < 8; ++fn) {
            const int col = warp_n * 64 + fn * 8 + (lane & 3) * 2;
            float2 lo, hi;
            lo.x = __int2float_rn(C[fm][fn][0]) * osc;
            lo.y = __int2float_rn(C[fm][fn][1]) * osc;
            hi.x = __int2float_rn(C[fm][fn][2]) * osc;
            hi.y = __int2float_rn(C[fm][fn][3]) * osc;
            *reinterpret_cast<float2*>(&stg[rbase * 136 + col])       = lo;
            *reinterpret_cast<float2*>(&stg[(rbase + 8) * 136 + col]) = hi;
        }
    }
    __syncthreads();
#pragma unroll
    for (int i = 0; i < 16; ++i) {
        int idx = i * 256 + tid;
        int rr = idx >> 5, cc = (idx & 31) * 4;
        float4 vv = *reinterpret_cast<float4*>(&stg[rr * 136 + cc]);
        *reinterpret_cast<float4*>(out + (size_t)(m0 + rr) * N_DIM + n0 + cc) = vv;
    }
}

// ============================================================================
// Launch
// ============================================================================
extern "C" void kernel_launch(void* const* d_in, const int* in_sizes, int n_in,
                              void* d_out, int out_size) {
    const float4* x4 = (const float4*)d_in[0];
    const float4* w4 = (const float4*)d_in[1];
    const float4* g4 = (const float4*)d_in[2];
    const float4* b4 = (const float4*)d_in[3];
    float* out = (float*)d_out;

    zero_kernel<<<1, 1>>>();
    ln_stats_kernel<<<M_ROWS, 256>>>(x4, g4, b4);
    wabs_kernel<<<256, 256>>>(w4);
    wtern_kernel<<<(N_DIM * K_DIM / 4) / 256, 256>>>(w4);
    finalize_kernel<<<1, 1>>>();
    quant_kernel<<<(M_ROWS * K_DIM / 4) / 256, 256>>>(x4, g4, b4);

    static bool attr_set = false;
    if (!attr_set) {
        cudaFuncSetAttribute(gemm_kernel,
                             cudaFuncAttributeMaxDynamicSharedMemorySize, GEMM_SMEM);
        attr_set = true;
    }
    dim3 grid(N_DIM / 128, M_ROWS / 128);
    gemm_kernel<<<grid, 256, GEMM_SMEM>>>(out);
}

// round 3
// speedup vs baseline: 1.3450x; 1.3450x over previous
#include <cuda_runtime.h>
#include <cuda_bf16.h>
#include <cstdint>

// ============================================================================
// BitLinear: x[4,8192,1024] f32, W[1024,1024] f32, gamma/beta[1024]
// out = (scale_act*alpha) * (Qint @ T^T);  M=32768, K=1024, N=1024
// R3 experiment: rows [0,16K) -> int8 mma.sync GEMM
//                rows [16K,32K) -> bf16 mma.sync GEMM (exact)
// Wall-time delta tells us the relative HMMA vs IMMA rate on sm_103.
// ============================================================================

#define M_ROWS 32768
#define K_DIM  1024
#define N_DIM  1024
#define M_HALF 16384

// ---------------- device scratch ----------------
__device__ float         g_mu[M_ROWS];
__device__ float         g_rstd[M_ROWS];
__device__ unsigned int  g_absmax_bits;
__device__ float         g_wsum_abs;
__device__ float         g_wsum_absmask;
__device__ float         g_wsum_maskcnt;
__device__ float         g_outscale;
__device__ float         g_qinv;
__device__ int8_t        g_q[(size_t)M_HALF * K_DIM];            // 16 MB (low half)
__device__ __nv_bfloat16 g_qb[(size_t)M_HALF * K_DIM];           // 32 MB (high half)
__device__ int8_t        g_t[(size_t)N_DIM * K_DIM];             // 1 MB
__device__ __nv_bfloat16 g_tb[(size_t)N_DIM * K_DIM];            // 2 MB

// ---------------- PTX helpers (baseline ISA) --------------------------------
__device__ __forceinline__ uint32_t smem_u32(const void* p) {
    uint32_t a;
    asm("{ .reg .u64 t; cvta.to.shared.u64 t, %1; cvt.u32.u64 %0, t; }"
        : "=r"(a) : "l"(p));
    return a;
}
__device__ __forceinline__ void ldm_x4(uint32_t* r, uint32_t addr) {
    asm volatile("ldmatrix.sync.aligned.m8n8.x4.shared.b16 {%0,%1,%2,%3}, [%4];"
                 : "=r"(r[0]), "=r"(r[1]), "=r"(r[2]), "=r"(r[3]) : "r"(addr));
}
__device__ __forceinline__ void mma_s8(int* c, const uint32_t* a, const uint32_t* b) {
    asm volatile(
        "mma.sync.aligned.m16n8k32.row.col.s32.s8.s8.s32 "
        "{%0,%1,%2,%3}, {%4,%5,%6,%7}, {%8,%9}, {%0,%1,%2,%3};"
        : "+r"(c[0]), "+r"(c[1]), "+r"(c[2]), "+r"(c[3])
        : "r"(a[0]), "r"(a[1]), "r"(a[2]), "r"(a[3]), "r"(b[0]), "r"(b[1]));
}
__device__ __forceinline__ void mma_bf16(float* c, const uint32_t* a, const uint32_t* b) {
    asm volatile(
        "mma.sync.aligned.m16n8k16.row.col.f32.bf16.bf16.f32 "
        "{%0,%1,%2,%3}, {%4,%5,%6,%7}, {%8,%9}, {%0,%1,%2,%3};"
        : "+f"(c[0]), "+f"(c[1]), "+f"(c[2]), "+f"(c[3])
        : "r"(a[0]), "r"(a[1]), "r"(a[2]), "r"(a[3]), "r"(b[0]), "r"(b[1]));
}
#define CP_ASYNC16(sm, gm)                                                   \
    asm volatile("cp.async.cg.shared.global [%0], [%1], 16;" ::              \
                 "r"(sm), "l"(__cvta_generic_to_global(gm)))
#define CP_COMMIT() asm volatile("cp.async.commit_group;" ::: "memory")
#define CP_WAIT(n)  asm volatile("cp.async.wait_group %0;" :: "n"(n) : "memory")

// ============================================================================
// Kernel 1: zero accumulators
// ============================================================================
__global__ void zero_kernel() {
    g_absmax_bits  = 0u;
    g_wsum_abs     = 0.0f;
    g_wsum_absmask = 0.0f;
    g_wsum_maskcnt = 0.0f;
}

// ============================================================================
// Kernel 2: LN stats per row + global absmax of normalized output
// ============================================================================
__global__ __launch_bounds__(256) void ln_stats_kernel(
    const float4* __restrict__ x4, const float4* __restrict__ gamma4,
    const float4* __restrict__ beta4) {
    const int row = blockIdx.x;
    const int tid = threadIdx.x;
    float4 v = x4[(size_t)row * 256 + tid];
    float s  = v.x + v.y + v.z + v.w;
    float ss = fmaf(v.x, v.x, fmaf(v.y, v.y, fmaf(v.z, v.z, v.w * v.w)));
#pragma unroll
    for (int o = 16; o > 0; o >>= 1) {
        s  += __shfl_xor_sync(0xffffffffu, s, o);
        ss += __shfl_xor_sync(0xffffffffu, ss, o);
    }
    __shared__ float rs[8], rss[8], bc[2], rm[8];
    const int w = tid >> 5, lane = tid & 31;
    if (lane == 0) { rs[w] = s; rss[w] = ss; }
    __syncthreads();
    if (tid == 0) {
        float ts = 0.f, tss = 0.f;
#pragma unroll
        for (int i = 0; i < 8; ++i) { ts += rs[i]; tss += rss[i]; }
        float mu  = ts * (1.0f / 1024.0f);
        float var = tss * (1.0f / 1024.0f) - mu * mu;
        float rstd = rsqrtf(var + 1e-5f);
        bc[0] = mu; bc[1] = rstd;
        g_mu[row] = mu; g_rstd[row] = rstd;
    }
    __syncthreads();
    const float mu = bc[0], rstd = bc[1];
    float4 g = gamma4[tid], b = beta4[tid];
    float m0 = fabsf(fmaf((v.x - mu) * rstd, g.x, b.x));
    float m1 = fabsf(fmaf((v.y - mu) * rstd, g.y, b.y));
    float m2 = fabsf(fmaf((v.z - mu) * rstd, g.z, b.z));
    float m3 = fabsf(fmaf((v.w - mu) * rstd, g.w, b.w));
    float mm = fmaxf(fmaxf(m0, m1), fmaxf(m2, m3));
#pragma unroll
    for (int o = 16; o > 0; o >>= 1)
        mm = fmaxf(mm, __shfl_xor_sync(0xffffffffu, mm, o));
    if (lane == 0) rm[w] = mm;
    __syncthreads();
    if (tid == 0) {
        float t = rm[0];
#pragma unroll
        for (int i = 1; i < 8; ++i) t = fmaxf(t, rm[i]);
        atomicMax(&g_absmax_bits, __float_as_uint(t));
    }
}

// ============================================================================
// Kernel 3: sum |W|
// ============================================================================
__global__ __launch_bounds__(256) void wabs_kernel(const float4* __restrict__ w4) {
    float s = 0.f;
    for (int i = blockIdx.x * blockDim.x + threadIdx.x; i < (N_DIM * K_DIM / 4);
         i += gridDim.x * blockDim.x) {
        float4 v = w4[i];
        s += fabsf(v.x) + fabsf(v.y) + fabsf(v.z) + fabsf(v.w);
    }
#pragma unroll
    for (int o = 16; o > 0; o >>= 1) s += __shfl_xor_sync(0xffffffffu, s, o);
    __shared__ float rr[8];
    if ((threadIdx.x & 31) == 0) rr[threadIdx.x >> 5] = s;
    __syncthreads();
    if (threadIdx.x == 0) {
        float t = 0.f;
#pragma unroll
        for (int i = 0; i < 8; ++i) t += rr[i];
        atomicAdd(&g_wsum_abs, t);
    }
}

// ============================================================================
// Kernel 4: ternarize W -> int8 {-1,0,+1} AND bf16; reduce masked sums
// ============================================================================
__global__ __launch_bounds__(256) void wtern_kernel(const float4* __restrict__ w4) {
    const int idx = blockIdx.x * 256 + threadIdx.x;
    const float delta = 0.7f * g_wsum_abs * (1.0f / (float)(N_DIM * K_DIM));
    float4 v = w4[idx];
    float a[4] = {v.x, v.y, v.z, v.w};
    float tf[4];
    float sa = 0.f, cnt = 0.f;
#pragma unroll
    for (int j = 0; j < 4; ++j) {
        float av = fabsf(a[j]);
        if (av > delta) {
            tf[j] = (a[j] > 0.f) ? 1.0f : -1.0f;
            sa += av; cnt += 1.0f;
        } else tf[j] = 0.0f;
    }
    int t0 = (int)tf[0], t1 = (int)tf[1], t2 = (int)tf[2], t3 = (int)tf[3];
    uint32_t pk = (uint32_t)(t0 & 0xff) | ((uint32_t)(t1 & 0xff) << 8) |
                  ((uint32_t)(t2 & 0xff) << 16) | ((uint32_t)t3 << 24);
    reinterpret_cast<uint32_t*>(g_t)[idx] = pk;
    __nv_bfloat162 p0 = __floats2bfloat162_rn(tf[0], tf[1]);
    __nv_bfloat162 p1 = __floats2bfloat162_rn(tf[2], tf[3]);
    uint2 pb;
    pb.x = *reinterpret_cast<uint32_t*>(&p0);
    pb.y = *reinterpret_cast<uint32_t*>(&p1);
    reinterpret_cast<uint2*>(g_tb)[idx] = pb;
#pragma unroll
    for (int o = 16; o > 0; o >>= 1) {
        sa  += __shfl_xor_sync(0xffffffffu, sa, o);
        cnt += __shfl_xor_sync(0xffffffffu, cnt, o);
    }
    __shared__ float ra[8], rc[8];
    if ((threadIdx.x & 31) == 0) { ra[threadIdx.x >> 5] = sa; rc[threadIdx.x >> 5] = cnt; }
    __syncthreads();
    if (threadIdx.x == 0) {
        float ta = 0.f, tc = 0.f;
#pragma unroll
        for (int i = 0; i < 8; ++i) { ta += ra[i]; tc += rc[i]; }
        atomicAdd(&g_wsum_absmask, ta);
        atomicAdd(&g_wsum_maskcnt, tc);
    }
}

// ============================================================================
// Kernel 5: finalize scalars
// ============================================================================
__global__ void finalize_kernel() {
    float amax  = fmaxf(__uint_as_float(g_absmax_bits), 1e-8f);
    float scale = amax * (1.0f / 127.0f);
    float alpha = g_wsum_absmask / fmaxf(g_wsum_maskcnt, 1.0f);
    g_outscale = scale * alpha;
    g_qinv     = 127.0f / amax;
}

// ============================================================================
// Kernel 6: quantize LN(x). rows [0,16K) -> int8 codes; [16K,32K) -> bf16 codes
// ============================================================================
__global__ __launch_bounds__(256) void quant_kernel(
    const float4* __restrict__ x4, const float4* __restrict__ gamma4,
    const float4* __restrict__ beta4) {
    const int idx = blockIdx.x * 256 + threadIdx.x;
    const int row = idx >> 8;
    const int c4  = idx & 255;
    const float mu = g_mu[row], rstd = g_rstd[row], inv = g_qinv;
    float4 v = x4[idx];
    float4 g = gamma4[c4], b = beta4[c4];
    float q0 = rintf(fminf(fmaxf(fmaf((v.x - mu) * rstd, g.x, b.x) * inv, -127.f), 127.f));
    float q1 = rintf(fminf(fmaxf(fmaf((v.y - mu) * rstd, g.y, b.y) * inv, -127.f), 127.f));
    float q2 = rintf(fminf(fmaxf(fmaf((v.z - mu) * rstd, g.z, b.z) * inv, -127.f), 127.f));
    float q3 = rintf(fminf(fmaxf(fmaf((v.w - mu) * rstd, g.w, b.w) * inv, -127.f), 127.f));
    if (row < M_HALF) {
        int i0 = (int)q0, i1 = (int)q1, i2 = (int)q2, i3 = (int)q3;
        uint32_t pk = (uint32_t)(i0 & 0xff) | ((uint32_t)(i1 & 0xff) << 8) |
                      ((uint32_t)(i2 & 0xff) << 16) | ((uint32_t)i3 << 24);
        reinterpret_cast<uint32_t*>(g_q)[idx] = pk;
    } else {
        __nv_bfloat162 p0 = __floats2bfloat162_rn(q0, q1);
        __nv_bfloat162 p1 = __floats2bfloat162_rn(q2, q3);
        uint2 pb;
        pb.x = *reinterpret_cast<uint32_t*>(&p0);
        pb.y = *reinterpret_cast<uint32_t*>(&p1);
        reinterpret_cast<uint2*>(g_qb)[idx - (M_HALF * 256)] = pb;
    }
}

// ============================================================================
// GEMM common: CTA tile 128x128, 8 warps (4M x 2N), 3-stage cp.async, 96KB smem
// rows are 128 bytes (int8: k128 / bf16: k64); identical swizzle + ldmatrix map
// ============================================================================
#define GEMM_STAGES 3
#define STAGE_BYTES 32768
#define GEMM_SMEM   (GEMM_STAGES * STAGE_BYTES)

static __device__ __forceinline__ void load_stage_b(
    const uint8_t* __restrict__ Ag, const uint8_t* __restrict__ Bg,
    size_t row_stride, uint32_t sA, uint32_t sB, int kt, int tid) {
    const int koff = kt * 128;   // bytes
#pragma unroll
    for (int i = 0; i < 4; ++i) {
        int v = i * 256 + tid;
        int row = v >> 3, c = v & 7;
        uint32_t sw = (uint32_t)(row * 128 + ((c ^ (row & 7)) << 4));
        size_t go = (size_t)row * row_stride + koff + c * 16;
        CP_ASYNC16(sA + sw, Ag + go);
        CP_ASYNC16(sB + sw, Bg + go);
    }
}

// ---------------- int8 GEMM (rows [0, M_HALF)) ------------------------------
__global__ __launch_bounds__(256, 2) void gemm_i8_kernel(float* __restrict__ out) {
    extern __shared__ char smem[];
    const uint32_t smem_base = smem_u32(smem);
    const int tid = threadIdx.x;
    const int wid = tid >> 5, lane = tid & 31;
    const int warp_m = wid & 3, warp_n = wid >> 2;
    const int m0 = blockIdx.y * 128, n0 = blockIdx.x * 128;

    const uint8_t* Ag = reinterpret_cast<const uint8_t*>(g_q) + (size_t)m0 * K_DIM;
    const uint8_t* Bg = reinterpret_cast<const uint8_t*>(g_t) + (size_t)n0 * K_DIM;

    load_stage_b(Ag, Bg, K_DIM, smem_base, smem_base + 16384, 0, tid);
    CP_COMMIT();
    load_stage_b(Ag, Bg, K_DIM, smem_base + STAGE_BYTES, smem_base + STAGE_BYTES + 16384, 1, tid);
    CP_COMMIT();

    int C[2][8][4];
#pragma unroll
    for (int i = 0; i < 2; ++i)
#pragma unroll
        for (int j = 0; j < 8; ++j)
#pragma unroll
            for (int k = 0; k < 4; ++k) C[i][j][k] = 0;

    const int rA  = warp_m * 32 + (lane & 15);
    const int cA  = (lane >> 4);
    const int rBo = ((lane & 16) >> 1) + (lane & 7);
    const int cB  = (lane >> 3) & 1;

#pragma unroll 1
    for (int kt = 0; kt < 8; ++kt) {
        CP_WAIT(1);
        __syncthreads();
        if (kt + 2 < 8) {
            uint32_t sbase = smem_base + ((kt + 2) % GEMM_STAGES) * STAGE_BYTES;
            load_stage_b(Ag, Bg, K_DIM, sbase, sbase + 16384, kt + 2, tid);
        }
        CP_COMMIT();

        const uint32_t aB = smem_base + (kt % GEMM_STAGES) * STAGE_BYTES;
        const uint32_t bB = aB + 16384;
#pragma unroll
        for (int ks = 0; ks < 4; ++ks) {
            uint32_t a[2][4];
#pragma unroll
            for (int fm = 0; fm < 2; ++fm) {
                int row = rA + fm * 16;
                ldm_x4(a[fm], aB + row * 128 + (((ks * 2 + cA) ^ (row & 7)) << 4));
            }
            uint32_t b[4][4];
#pragma unroll
            for (int p = 0; p < 4; ++p) {
                int row = warp_n * 64 + p * 16 + rBo;
                ldm_x4(b[p], bB + row * 128 + (((ks * 2 + cB) ^ (row & 7)) << 4));
            }
#pragma unroll
            for (int fm = 0; fm < 2; ++fm)
#pragma unroll
                for (int p = 0; p < 4; ++p) {
                    mma_s8(C[fm][2 * p],     a[fm], &b[p][0]);
                    mma_s8(C[fm][2 * p + 1], a[fm], &b[p][2]);
                }
        }
        __syncthreads();
    }

    const float osc = g_outscale;
    float* stg = reinterpret_cast<float*>(smem);
    __syncthreads();
#pragma unroll
    for (int fm = 0; fm < 2; ++fm) {
        const int rbase = warp_m * 32 + fm * 16 + (lane >> 2);
#pragma unroll
        for (int fn = 0; fn < 8; ++fn) {
            const int col = warp_n * 64 + fn * 8 + (lane & 3) * 2;
            float2 lo, hi;
            lo.x = __int2float_rn(C[fm][fn][0]) * osc;
            lo.y = __int2float_rn(C[fm][fn][1]) * osc;
            hi.x = __int2float_rn(C[fm][fn][2]) * osc;
            hi.y = __int2float_rn(C[fm][fn][3]) * osc;
            *reinterpret_cast<float2*>(&stg[rbase * 136 + col])       = lo;
            *reinterpret_cast<float2*>(&stg[(rbase + 8) * 136 + col]) = hi;
        }
    }
    __syncthreads();
#pragma unroll
    for (int i = 0; i < 16; ++i) {
        int idx = i * 256 + tid;
        int rr = idx >> 5, cc = (idx & 31) * 4;
        float4 vv = *reinterpret_cast<float4*>(&stg[rr * 136 + cc]);
        *reinterpret_cast<float4*>(out + (size_t)(m0 + rr) * N_DIM + n0 + cc) = vv;
    }
}

// ---------------- bf16 GEMM (rows [M_HALF, M_ROWS)) -------------------------
__global__ __launch_bounds__(256, 2) void gemm_bf_kernel(float* __restrict__ out) {
    extern __shared__ char smem[];
    const uint32_t smem_base = smem_u32(smem);
    const int tid = threadIdx.x;
    const int wid = tid >> 5, lane = tid & 31;
    const int warp_m = wid & 3, warp_n = wid >> 2;
    const int m0 = blockIdx.y * 128, n0 = blockIdx.x * 128;   // m0 local to half

    const uint8_t* Ag = reinterpret_cast<const uint8_t*>(g_qb) + (size_t)m0 * K_DIM * 2;
    const uint8_t* Bg = reinterpret_cast<const uint8_t*>(g_tb) + (size_t)n0 * K_DIM * 2;

    load_stage_b(Ag, Bg, K_DIM * 2, smem_base, smem_base + 16384, 0, tid);
    CP_COMMIT();
    load_stage_b(Ag, Bg, K_DIM * 2, smem_base + STAGE_BYTES, smem_base + STAGE_BYTES + 16384, 1, tid);
    CP_COMMIT();

    float C[2][8][4];
#pragma unroll
    for (int i = 0; i < 2; ++i)
#pragma unroll
        for (int j = 0; j < 8; ++j)
#pragma unroll
            for (int k = 0; k < 4; ++k) C[i][j][k] = 0.0f;

    const int rA  = warp_m * 32 + (lane & 15);
    const int cA  = (lane >> 4);
    const int rBo = ((lane & 16) >> 1) + (lane & 7);
    const int cB  = (lane >> 3) & 1;

#pragma unroll 1
    for (int kt = 0; kt < 16; ++kt) {            // 16 chunks of k64 (128B)
        CP_WAIT(1);
        __syncthreads();
        if (kt + 2 < 16) {
            uint32_t sbase = smem_base + ((kt + 2) % GEMM_STAGES) * STAGE_BYTES;
            load_stage_b(Ag, Bg, K_DIM * 2, sbase, sbase + 16384, kt + 2, tid);
        }
        CP_COMMIT();

        const uint32_t aB = smem_base + (kt % GEMM_STAGES) * STAGE_BYTES;
        const uint32_t bB = aB + 16384;
#pragma unroll
        for (int ks = 0; ks < 4; ++ks) {         // 4 k16-steps per chunk
            uint32_t a[2][4];
#pragma unroll
            for (int fm = 0; fm < 2; ++fm) {
                int row = rA + fm * 16;
                ldm_x4(a[fm], aB + row * 128 + (((ks * 2 + cA) ^ (row & 7)) << 4));
            }
            uint32_t b[4][4];
#pragma unroll
            for (int p = 0; p < 4; ++p) {
                int row = warp_n * 64 + p * 16 + rBo;
                ldm_x4(b[p], bB + row * 128 + (((ks * 2 + cB) ^ (row & 7)) << 4));
            }
#pragma unroll
            for (int fm = 0; fm < 2; ++fm)
#pragma unroll
                for (int p = 0; p < 4; ++p) {
                    mma_bf16(C[fm][2 * p],     a[fm], &b[p][0]);
                    mma_bf16(C[fm][2 * p + 1], a[fm], &b[p][2]);
                }
        }
        __syncthreads();
    }

    const float osc = g_outscale;
    float* stg = reinterpret_cast<float*>(smem);
    __syncthreads();
#pragma unroll
    for (int fm = 0; fm < 2; ++fm) {
        const int rbase = warp_m * 32 + fm * 16 + (lane >> 2);
#pragma unroll
        for (int fn = 0; fn < 8; ++fn) {
            const int col = warp_n * 64 + fn * 8 + (lane & 3) * 2;
            float2 lo, hi;
            lo.x = C[fm][fn][0] * osc;
            lo.y = C[fm][fn][1] * osc;
            hi.x = C[fm][fn][2] * osc;
            hi.y = C[fm][fn][3] * osc;
            *reinterpret_cast<float2*>(&stg[rbase * 136 + col])       = lo;
            *reinterpret_cast<float2*>(&stg[(rbase + 8) * 136 + col]) = hi;
        }
    }
    __syncthreads();
#pragma unroll
    for (int i = 0; i < 16; ++i) {
        int idx = i * 256 + tid;
        int rr = idx >> 5, cc = (idx & 31) * 4;
        float4 vv = *reinterpret_cast<float4*>(&stg[rr * 136 + cc]);
        *reinterpret_cast<float4*>(out + (size_t)(M_HALF + m0 + rr) * N_DIM + n0 + cc) = vv;
    }
}

// ============================================================================
// Launch
// ============================================================================
extern "C" void kernel_launch(void* const* d_in, const int* in_sizes, int n_in,
                              void* d_out, int out_size) {
    const float4* x4 = (const float4*)d_in[0];
    const float4* w4 = (const float4*)d_in[1];
    const float4* g4 = (const float4*)d_in[2];
    const float4* b4 = (const float4*)d_in[3];
    float* out = (float*)d_out;

    zero_kernel<<<1, 1>>>();
    ln_stats_kernel<<<M_ROWS, 256>>>(x4, g4, b4);
    wabs_kernel<<<256, 256>>>(w4);
    wtern_kernel<<<(N_DIM * K_DIM / 4) / 256, 256>>>(w4);
    finalize_kernel<<<1, 1>>>();
    quant_kernel<<<(M_ROWS * K_DIM / 4) / 256, 256>>>(x4, g4, b4);

    static bool attr_set = false;
    if (!attr_set) {
        cudaFuncSetAttribute(gemm_i8_kernel,
                             cudaFuncAttributeMaxDynamicSharedMemorySize, GEMM_SMEM);
        cudaFuncSetAttribute(gemm_bf_kernel,
                             cudaFuncAttributeMaxDynamicSharedMemorySize, GEMM_SMEM);
        attr_set = true;
    }
    dim3 grid(N_DIM / 128, M_HALF / 128);
    gemm_i8_kernel<<<grid, 256, GEMM_SMEM>>>(out);
    gemm_bf_kernel<<<grid, 256, GEMM_SMEM>>>(out);
}

// round 4
// speedup vs baseline: 2.1224x; 1.5780x over previous
#include <cuda_runtime.h>
#include <cuda_bf16.h>
#include <cstdint>

// ============================================================================
// BitLinear: x[4,8192,1024] f32, W[1024,1024] f32, gamma/beta[1024]
// out = (scale_act*alpha) * (Qint @ T^T);  M=32768, K=1024, N=1024
// R4: all-bf16 path. Qint in [-127,127] and T in {-1,0,1} are exact in bf16;
// f32 accumulation exact (|sum| <= 130048 < 2^24). GEMM via mma.sync bf16
// (HMMA, measured ~2.4x the int8 mma rate on sm_103 baseline ISA).
// ============================================================================

#define M_ROWS 32768
#define K_DIM  1024
#define N_DIM  1024

// ---------------- device scratch ----------------
__device__ float         g_mu[M_ROWS];
__device__ float         g_rstd[M_ROWS];
__device__ unsigned int  g_absmax_bits;
__device__ float         g_wsum_abs;
__device__ float         g_wsum_absmask;
__device__ float         g_wsum_maskcnt;
__device__ float         g_outscale;
__device__ float         g_qinv;
__device__ __nv_bfloat16 g_qb[(size_t)M_ROWS * K_DIM];   // 64 MB
__device__ __nv_bfloat16 g_tb[(size_t)N_DIM * K_DIM];    // 2 MB

// ---------------- PTX helpers (baseline ISA) --------------------------------
__device__ __forceinline__ uint32_t smem_u32(const void* p) {
    uint32_t a;
    asm("{ .reg .u64 t; cvta.to.shared.u64 t, %1; cvt.u32.u64 %0, t; }"
        : "=r"(a) : "l"(p));
    return a;
}
__device__ __forceinline__ void ldm_x4(uint32_t* r, uint32_t addr) {
    asm volatile("ldmatrix.sync.aligned.m8n8.x4.shared.b16 {%0,%1,%2,%3}, [%4];"
                 : "=r"(r[0]), "=r"(r[1]), "=r"(r[2]), "=r"(r[3]) : "r"(addr));
}
__device__ __forceinline__ void mma_bf16(float* c, const uint32_t* a, const uint32_t* b) {
    asm volatile(
        "mma.sync.aligned.m16n8k16.row.col.f32.bf16.bf16.f32 "
        "{%0,%1,%2,%3}, {%4,%5,%6,%7}, {%8,%9}, {%0,%1,%2,%3};"
        : "+f"(c[0]), "+f"(c[1]), "+f"(c[2]), "+f"(c[3])
        : "r"(a[0]), "r"(a[1]), "r"(a[2]), "r"(a[3]), "r"(b[0]), "r"(b[1]));
}
#define CP_ASYNC16(sm, gm)                                                   \
    asm volatile("cp.async.cg.shared.global [%0], [%1], 16;" ::              \
                 "r"(sm), "l"(__cvta_generic_to_global(gm)))
#define CP_COMMIT() asm volatile("cp.async.commit_group;" ::: "memory")
#define CP_WAIT(n)  asm volatile("cp.async.wait_group %0;" :: "n"(n) : "memory")

// ============================================================================
// Kernel 1: zero accumulators
// ============================================================================
__global__ void zero_kernel() {
    g_absmax_bits  = 0u;
    g_wsum_abs     = 0.0f;
    g_wsum_absmask = 0.0f;
    g_wsum_maskcnt = 0.0f;
}

// ============================================================================
// Kernel 2: LN stats per row + global absmax of normalized output
// ============================================================================
__global__ __launch_bounds__(256) void ln_stats_kernel(
    const float4* __restrict__ x4, const float4* __restrict__ gamma4,
    const float4* __restrict__ beta4) {
    const int row = blockIdx.x;
    const int tid = threadIdx.x;
    float4 v = x4[(size_t)row * 256 + tid];
    float s  = v.x + v.y + v.z + v.w;
    float ss = fmaf(v.x, v.x, fmaf(v.y, v.y, fmaf(v.z, v.z, v.w * v.w)));
#pragma unroll
    for (int o = 16; o > 0; o >>= 1) {
        s  += __shfl_xor_sync(0xffffffffu, s, o);
        ss += __shfl_xor_sync(0xffffffffu, ss, o);
    }
    __shared__ float rs[8], rss[8], bc[2], rm[8];
    const int w = tid >> 5, lane = tid & 31;
    if (lane == 0) { rs[w] = s; rss[w] = ss; }
    __syncthreads();
    if (tid == 0) {
        float ts = 0.f, tss = 0.f;
#pragma unroll
        for (int i = 0; i < 8; ++i) { ts += rs[i]; tss += rss[i]; }
        float mu  = ts * (1.0f / 1024.0f);
        float var = tss * (1.0f / 1024.0f) - mu * mu;
        float rstd = rsqrtf(var + 1e-5f);
        bc[0] = mu; bc[1] = rstd;
        g_mu[row] = mu; g_rstd[row] = rstd;
    }
    __syncthreads();
    const float mu = bc[0], rstd = bc[1];
    float4 g = gamma4[tid], b = beta4[tid];
    float m0 = fabsf(fmaf((v.x - mu) * rstd, g.x, b.x));
    float m1 = fabsf(fmaf((v.y - mu) * rstd, g.y, b.y));
    float m2 = fabsf(fmaf((v.z - mu) * rstd, g.z, b.z));
    float m3 = fabsf(fmaf((v.w - mu) * rstd, g.w, b.w));
    float mm = fmaxf(fmaxf(m0, m1), fmaxf(m2, m3));
#pragma unroll
    for (int o = 16; o > 0; o >>= 1)
        mm = fmaxf(mm, __shfl_xor_sync(0xffffffffu, mm, o));
    if (lane == 0) rm[w] = mm;
    __syncthreads();
    if (tid == 0) {
        float t = rm[0];
#pragma unroll
        for (int i = 1; i < 8; ++i) t = fmaxf(t, rm[i]);
        atomicMax(&g_absmax_bits, __float_as_uint(t));
    }
}

// ============================================================================
// Kernel 3: sum |W|
// ============================================================================
__global__ __launch_bounds__(256) void wabs_kernel(const float4* __restrict__ w4) {
    float s = 0.f;
    for (int i = blockIdx.x * blockDim.x + threadIdx.x; i < (N_DIM * K_DIM / 4);
         i += gridDim.x * blockDim.x) {
        float4 v = w4[i];
        s += fabsf(v.x) + fabsf(v.y) + fabsf(v.z) + fabsf(v.w);
    }
#pragma unroll
    for (int o = 16; o > 0; o >>= 1) s += __shfl_xor_sync(0xffffffffu, s, o);
    __shared__ float rr[8];
    if ((threadIdx.x & 31) == 0) rr[threadIdx.x >> 5] = s;
    __syncthreads();
    if (threadIdx.x == 0) {
        float t = 0.f;
#pragma unroll
        for (int i = 0; i < 8; ++i) t += rr[i];
        atomicAdd(&g_wsum_abs, t);
    }
}

// ============================================================================
// Kernel 4: ternarize W -> bf16 {-1,0,+1}; reduce masked |W| sum + count
// ============================================================================
__global__ __launch_bounds__(256) void wtern_kernel(const float4* __restrict__ w4) {
    const int idx = blockIdx.x * 256 + threadIdx.x;
    const float delta = 0.7f * g_wsum_abs * (1.0f / (float)(N_DIM * K_DIM));
    float4 v = w4[idx];
    float a[4] = {v.x, v.y, v.z, v.w};
    float tf[4];
    float sa = 0.f, cnt = 0.f;
#pragma unroll
    for (int j = 0; j < 4; ++j) {
        float av = fabsf(a[j]);
        if (av > delta) {
            tf[j] = (a[j] > 0.f) ? 1.0f : -1.0f;
            sa += av; cnt += 1.0f;
        } else tf[j] = 0.0f;
    }
    __nv_bfloat162 p0 = __floats2bfloat162_rn(tf[0], tf[1]);
    __nv_bfloat162 p1 = __floats2bfloat162_rn(tf[2], tf[3]);
    uint2 pb;
    pb.x = *reinterpret_cast<uint32_t*>(&p0);
    pb.y = *reinterpret_cast<uint32_t*>(&p1);
    reinterpret_cast<uint2*>(g_tb)[idx] = pb;
#pragma unroll
    for (int o = 16; o > 0; o >>= 1) {
        sa  += __shfl_xor_sync(0xffffffffu, sa, o);
        cnt += __shfl_xor_sync(0xffffffffu, cnt, o);
    }
    __shared__ float ra[8], rc[8];
    if ((threadIdx.x & 31) == 0) { ra[threadIdx.x >> 5] = sa; rc[threadIdx.x >> 5] = cnt; }
    __syncthreads();
    if (threadIdx.x == 0) {
        float ta = 0.f, tc = 0.f;
#pragma unroll
        for (int i = 0; i < 8; ++i) { ta += ra[i]; tc += rc[i]; }
        atomicAdd(&g_wsum_absmask, ta);
        atomicAdd(&g_wsum_maskcnt, tc);
    }
}

// ============================================================================
// Kernel 5: finalize scalars
// ============================================================================
__global__ void finalize_kernel() {
    float amax  = fmaxf(__uint_as_float(g_absmax_bits), 1e-8f);
    float scale = amax * (1.0f / 127.0f);
    float alpha = g_wsum_absmask / fmaxf(g_wsum_maskcnt, 1.0f);
    g_outscale = scale * alpha;
    g_qinv     = 127.0f / amax;
}

// ============================================================================
// Kernel 6: quantize LN(x) -> bf16 integer codes in [-127,127]
// ============================================================================
__global__ __launch_bounds__(256) void quant_kernel(
    const float4* __restrict__ x4, const float4* __restrict__ gamma4,
    const float4* __restrict__ beta4) {
    const int idx = blockIdx.x * 256 + threadIdx.x;
    const int row = idx >> 8;
    const int c4  = idx & 255;
    const float mu = g_mu[row], rstd = g_rstd[row], inv = g_qinv;
    float4 v = x4[idx];
    float4 g = gamma4[c4], b = beta4[c4];
    float q0 = rintf(fminf(fmaxf(fmaf((v.x - mu) * rstd, g.x, b.x) * inv, -127.f), 127.f));
    float q1 = rintf(fminf(fmaxf(fmaf((v.y - mu) * rstd, g.y, b.y) * inv, -127.f), 127.f));
    float q2 = rintf(fminf(fmaxf(fmaf((v.z - mu) * rstd, g.z, b.z) * inv, -127.f), 127.f));
    float q3 = rintf(fminf(fmaxf(fmaf((v.w - mu) * rstd, g.w, b.w) * inv, -127.f), 127.f));
    __nv_bfloat162 p0 = __floats2bfloat162_rn(q0, q1);
    __nv_bfloat162 p1 = __floats2bfloat162_rn(q2, q3);
    uint2 pb;
    pb.x = *reinterpret_cast<uint32_t*>(&p0);
    pb.y = *reinterpret_cast<uint32_t*>(&p1);
    reinterpret_cast<uint2*>(g_qb)[idx] = pb;
}

// ============================================================================
// Kernel 7: bf16 GEMM via mma.sync m16n8k16 (HMMA), f32 accum
// CTA tile 128x128, 8 warps (4M x 2N), warp tile 32x64
// K chunked by 128 B (k64), 3-stage cp.async pipeline, xor-swizzled smem
// ============================================================================
#define GEMM_STAGES 3
#define STAGE_BYTES 32768
#define GEMM_SMEM   (GEMM_STAGES * STAGE_BYTES)
#define NK_CHUNKS   16                    // 2048 B / 128 B

static __device__ __forceinline__ void load_stage(
    const uint8_t* __restrict__ Ag, const uint8_t* __restrict__ Bg,
    uint32_t sA, uint32_t sB, int kt, int tid) {
    const int koff = kt * 128;   // bytes
#pragma unroll
    for (int i = 0; i < 4; ++i) {
        int v = i * 256 + tid;
        int row = v >> 3, c = v & 7;
        uint32_t sw = (uint32_t)(row * 128 + ((c ^ (row & 7)) << 4));
        size_t go = (size_t)row * (K_DIM * 2) + koff + c * 16;
        CP_ASYNC16(sA + sw, Ag + go);
        CP_ASYNC16(sB + sw, Bg + go);
    }
}

__global__ __launch_bounds__(256, 2) void gemm_kernel(float* __restrict__ out) {
    extern __shared__ char smem[];
    const uint32_t smem_base = smem_u32(smem);
    const int tid = threadIdx.x;
    const int wid = tid >> 5, lane = tid & 31;
    const int warp_m = wid & 3, warp_n = wid >> 2;
    const int m0 = blockIdx.y * 128, n0 = blockIdx.x * 128;

    const uint8_t* Ag = reinterpret_cast<const uint8_t*>(g_qb) + (size_t)m0 * K_DIM * 2;
    const uint8_t* Bg = reinterpret_cast<const uint8_t*>(g_tb) + (size_t)n0 * K_DIM * 2;

    load_stage(Ag, Bg, smem_base, smem_base + 16384, 0, tid);
    CP_COMMIT();
    load_stage(Ag, Bg, smem_base + STAGE_BYTES, smem_base + STAGE_BYTES + 16384, 1, tid);
    CP_COMMIT();

    float C[2][8][4];
#pragma unroll
    for (int i = 0; i < 2; ++i)
#pragma unroll
        for (int j = 0; j < 8; ++j)
#pragma unroll
            for (int k = 0; k < 4; ++k) C[i][j][k] = 0.0f;

    const int rA  = warp_m * 32 + (lane & 15);
    const int cA  = (lane >> 4);
    const int rBo = ((lane & 16) >> 1) + (lane & 7);
    const int cB  = (lane >> 3) & 1;

#pragma unroll 1
    for (int kt = 0; kt < NK_CHUNKS; ++kt) {
        CP_WAIT(1);
        __syncthreads();
        if (kt + 2 < NK_CHUNKS) {
            uint32_t sbase = smem_base + ((kt + 2) % GEMM_STAGES) * STAGE_BYTES;
            load_stage(Ag, Bg, sbase, sbase + 16384, kt + 2, tid);
        }
        CP_COMMIT();

        const uint32_t aB = smem_base + (kt % GEMM_STAGES) * STAGE_BYTES;
        const uint32_t bB = aB + 16384;
#pragma unroll
        for (int ks = 0; ks < 4; ++ks) {         // 4 k16-steps per 128B chunk
            uint32_t a[2][4];
#pragma unroll
            for (int fm = 0; fm < 2; ++fm) {
                int row = rA + fm * 16;
                ldm_x4(a[fm], aB + row * 128 + (((ks * 2 + cA) ^ (row & 7)) << 4));
            }
            uint32_t b[4][4];
#pragma unroll
            for (int p = 0; p < 4; ++p) {
                int row = warp_n * 64 + p * 16 + rBo;
                ldm_x4(b[p], bB + row * 128 + (((ks * 2 + cB) ^ (row & 7)) << 4));
            }
#pragma unroll
            for (int fm = 0; fm < 2; ++fm)
#pragma unroll
                for (int p = 0; p < 4; ++p) {
                    mma_bf16(C[fm][2 * p],     a[fm], &b[p][0]);
                    mma_bf16(C[fm][2 * p + 1], a[fm], &b[p][2]);
                }
        }
        __syncthreads();
    }

    // epilogue: scale, stage through smem, coalesced float4 stores
    const float osc = g_outscale;
    float* stg = reinterpret_cast<float*>(smem);
    __syncthreads();
#pragma unroll
    for (int fm = 0; fm < 2; ++fm) {
        const int rbase = warp_m * 32 + fm * 16 + (lane >> 2);
#pragma unroll
        for (int fn = 0; fn < 8; ++fn) {
            const int col = warp_n * 64 + fn * 8 + (lane & 3) * 2;
            float2 lo, hi;
            lo.x = C[fm][fn][0] * osc;
            lo.y = C[fm][fn][1] * osc;
            hi.x = C[fm][fn][2] * osc;
            hi.y = C[fm][fn][3] * osc;
            *reinterpret_cast<float2*>(&stg[rbase * 136 + col])       = lo;
            *reinterpret_cast<float2*>(&stg[(rbase + 8) * 136 + col]) = hi;
        }
    }
    __syncthreads();
#pragma unroll
    for (int i = 0; i < 16; ++i) {
        int idx = i * 256 + tid;
        int rr = idx >> 5, cc = (idx & 31) * 4;
        float4 vv = *reinterpret_cast<float4*>(&stg[rr * 136 + cc]);
        *reinterpret_cast<float4*>(out + (size_t)(m0 + rr) * N_DIM + n0 + cc) = vv;
    }
}

// ============================================================================
// Launch
// ============================================================================
extern "C" void kernel_launch(void* const* d_in, const int* in_sizes, int n_in,
                              void* d_out, int out_size) {
    const float4* x4 = (const float4*)d_in[0];
    const float4* w4 = (const float4*)d_in[1];
    const float4* g4 = (const float4*)d_in[2];
    const float4* b4 = (const float4*)d_in[3];
    float* out = (float*)d_out;

    zero_kernel<<<1, 1>>>();
    ln_stats_kernel<<<M_ROWS, 256>>>(x4, g4, b4);
    wabs_kernel<<<256, 256>>>(w4);
    wtern_kernel<<<(N_DIM * K_DIM / 4) / 256, 256>>>(w4);
    finalize_kernel<<<1, 1>>>();
    quant_kernel<<<(M_ROWS * K_DIM / 4) / 256, 256>>>(x4, g4, b4);

    static bool attr_set = false;
    if (!attr_set) {
        cudaFuncSetAttribute(gemm_kernel,
                             cudaFuncAttributeMaxDynamicSharedMemorySize, GEMM_SMEM);
        attr_set = true;
    }
    dim3 grid(N_DIM / 128, M_ROWS / 128);
    gemm_kernel<<<grid, 256, GEMM_SMEM>>>(out);
}